// round 1
// baseline (speedup 1.0000x reference)
#include <cuda_runtime.h>
#include <math.h>

// ----------------------------------------------------------------------------
// NonLinearTSQ: gated tensor-square
//   in : 64x0e + 32x1o   (160 floats/node)
//   out: 64x0e + 32x1o + 16x2e (240 floats/node), B = 32768
//
// Factored algorithm (per node):
//   s = tanh(x[:64]); v[n] = x[64+3n:64+3n+3] * tanh(gates[n])
//   out0[p] = sum_k z[k] * Wc[k][p]          (packed sym features, K=2608)
//       z: 2080 ss pairs s_u*s_v (u<=v), 528 vv pairs dot(v_u,v_v) (u<=v)
//       Wc folds c0, 1/sqrt(3), and the symmetry doubling.
//   out1[q,i] = c1 * sum_v A[v,q]*v[v,i],  A[v,q] = sum_u s_u W_sv1[u,v,q]
//   out2: tv[u,j,r] = sum_v v[v,j] W_vv2[u,v,r];
//         S[r,i,j]  = sum_u v[u,i] tv[u,j,r];  out2[r,m] = c2 * S : CG
// ----------------------------------------------------------------------------

#define KSS   2080    // packed (u<=v) scalar-scalar pairs, 64 channels
#define KVV   528     // packed (u<=v) vector-vector pairs, 32 channels
#define KREAL 2608
#define KPAD  2624    // 41 chunks of 64

__device__ __align__(16) float g_Wc[KPAD * 64];
__device__ int g_pu[KPAD];
__device__ int g_pv[KPAD];

// ---------------------------------------------------------------- prep kernels
__global__ void prep_pairs()
{
    for (int k = threadIdx.x; k < KPAD; k += blockDim.x) {
        int u = 0, v = 0;
        if (k < KSS) {
            int rem = k, row = 64;
            while (rem >= row) { rem -= row; row--; }
            u = 64 - row; v = u + rem;
        } else if (k < KREAL) {
            int rem = k - KSS, row = 32;
            while (rem >= row) { rem -= row; row--; }
            u = 32 - row; v = u + rem;
        }
        g_pu[k] = u;
        g_pv[k] = v;
    }
}

__global__ void prep_wc(const float* __restrict__ Wss0,
                        const float* __restrict__ Wvv0)
{
    int k = blockIdx.x;       // 0..KPAD-1
    int p = threadIdx.x;      // 0..63
    const float C0 = 1.0f / sqrtf(5120.0f);       // 1/sqrt(64^2 + 32^2)
    const float RS3 = 0.5773502691896258f;        // 1/sqrt(3)
    float val = 0.0f;
    if (k < KSS) {
        int u = g_pu[k], v = g_pv[k];
        val = Wss0[(u * 64 + v) * 64 + p];
        if (u != v) val += Wss0[(v * 64 + u) * 64 + p];
        val *= C0;
    } else if (k < KREAL) {
        int u = g_pu[k], v = g_pv[k];
        val = Wvv0[(u * 32 + v) * 64 + p];
        if (u != v) val += Wvv0[(v * 32 + u) * 64 + p];
        val *= C0 * RS3;
    }
    g_Wc[k * 64 + p] = val;
}

// ------------------------------------------------------------------ main kernel
// 64 nodes per block, 256 threads.
// smem: sv[160][64] (40KB) | U[16640 floats] (65KB) | gv[32]
#define SMEM_FLOATS (160 * 64 + 16640 + 32)

__global__ __launch_bounds__(256, 2)
void k_main(const float* __restrict__ x, const float* __restrict__ gates,
            const float* __restrict__ Wsv1, const float* __restrict__ Wvv2,
            float* __restrict__ out, int B)
{
    extern __shared__ float sm[];
    float* sv = sm;                 // [160][64] feature-major
    float* U  = sm + 160 * 64;      // 16640 floats, multi-purpose
    float* gv = U + 16640;          // 32 floats

    const int tid = threadIdx.x;
    const int tx = tid & 15;        // output-column group
    const int ty = tid >> 4;        // node group
    const int node0 = blockIdx.x * 64;

    // ---- gate logits
    if (tid < 32) gv[tid] = tanhf(gates[tid]);
    __syncthreads();

    // ---- Phase 1: load tile, apply nonlinearity, transpose to feature-major
    for (int idx = tid; idx < 2560; idx += 256) {
        int node = idx / 40;
        int fq = idx - node * 40;
        float4 xv = make_float4(0.f, 0.f, 0.f, 0.f);
        if (node0 + node < B)
            xv = *(const float4*)(x + (size_t)(node0 + node) * 160 + fq * 4);
        float vals[4] = {xv.x, xv.y, xv.z, xv.w};
        #pragma unroll
        for (int jj = 0; jj < 4; jj++) {
            int f = fq * 4 + jj;
            float val = vals[jj];
            if (f < 64) val = tanhf(val);
            else        val *= gv[(f - 64) / 3];
            sv[f * 64 + node] = val;
        }
    }
    __syncthreads();

    // ---- Phase 2: out0 GEMM, K=2624 (padded), on-the-fly packed features
    float acc0[4][4];
    #pragma unroll
    for (int i = 0; i < 4; i++)
        #pragma unroll
        for (int j = 0; j < 4; j++) acc0[i][j] = 0.f;

    float* zbuf = U;          // [64 k][64 node]
    float* wbuf = U + 4096;   // [64 k][64 p]

    for (int ck = 0; ck < 41; ck++) {
        int kbase = ck * 64;
        // build feature chunk
        #pragma unroll
        for (int t = 0; t < 16; t++) {
            int idx = tid + t * 256;
            int kk = idx >> 6;
            int node = idx & 63;
            int k = kbase + kk;
            float z = 0.f;
            if (k < KSS) {
                int u = g_pu[k], v = g_pv[k];
                z = sv[u * 64 + node] * sv[v * 64 + node];
            } else if (k < KREAL) {
                int u = g_pu[k], v = g_pv[k];
                const float* pa = sv + (64 + 3 * u) * 64 + node;
                const float* pb = sv + (64 + 3 * v) * 64 + node;
                z = pa[0] * pb[0] + pa[64] * pb[64] + pa[128] * pb[128];
            }
            zbuf[kk * 64 + node] = z;
        }
        // stage weight chunk
        {
            const float4* wsrc = (const float4*)(g_Wc + kbase * 64);
            float4* wdst = (float4*)wbuf;
            #pragma unroll
            for (int t = 0; t < 4; t++) wdst[tid + t * 256] = wsrc[tid + t * 256];
        }
        __syncthreads();
        #pragma unroll 8
        for (int kk = 0; kk < 64; kk++) {
            float a[4], b[4];
            #pragma unroll
            for (int i = 0; i < 4; i++) a[i] = zbuf[kk * 64 + ty + 16 * i];
            #pragma unroll
            for (int j = 0; j < 4; j++) b[j] = wbuf[kk * 64 + tx + 16 * j];
            #pragma unroll
            for (int i = 0; i < 4; i++)
                #pragma unroll
                for (int j = 0; j < 4; j++) acc0[i][j] += a[i] * b[j];
        }
        __syncthreads();
    }
    // write out0 (constants already folded into Wc)
    #pragma unroll
    for (int i = 0; i < 4; i++) {
        int node = node0 + ty + 16 * i;
        if (node < B) {
            #pragma unroll
            for (int j = 0; j < 4; j++)
                out[(size_t)node * 240 + tx + 16 * j] = acc0[i][j];
        }
    }

    // ---- Phase 3: out1.  A[v,q]-GEMM in q-chunks of 8, then v-contraction.
    const float C1 = 0.022097086912079612f;   // 1/sqrt(2048)
    for (int qc = 0; qc < 4; qc++) {
        // stage W_sv1 slice: U[u*256 + (v*8+ql)]
        for (int idx = tid; idx < 16384; idx += 256) {
            int u = idx >> 8;
            int c = idx & 255;
            int v = c >> 3, ql = c & 7;
            U[idx] = Wsv1[(u * 32 + v) * 32 + qc * 8 + ql];
        }
        __syncthreads();
        float acc[4][16];
        #pragma unroll
        for (int i = 0; i < 4; i++)
            #pragma unroll
            for (int j = 0; j < 16; j++) acc[i][j] = 0.f;
        #pragma unroll 4
        for (int k = 0; k < 64; k++) {
            float a[4], b[16];
            #pragma unroll
            for (int i = 0; i < 4; i++) a[i] = sv[k * 64 + ty + 16 * i];
            #pragma unroll
            for (int j = 0; j < 16; j++) b[j] = U[k * 256 + tx + 16 * j];
            #pragma unroll
            for (int i = 0; i < 4; i++)
                #pragma unroll
                for (int j = 0; j < 16; j++) acc[i][j] += a[i] * b[j];
        }
        __syncthreads();
        // stage A chunk (pitch 65 vs 64 to avoid bank conflicts)
        #pragma unroll
        for (int i = 0; i < 4; i++)
            #pragma unroll
            for (int j = 0; j < 16; j++)
                U[(tx + 16 * j) * 65 + ty + 16 * i] = acc[i][j];
        __syncthreads();
        // epilogue: out1[q,i] = C1 * sum_v A[v,q] v[v,i]
        #pragma unroll
        for (int t = 0; t < 2; t++) {
            int it = tid + t * 256;        // 512 items: (node, ql)
            int node = it & 63;
            int ql = it >> 6;
            float o0 = 0.f, o1 = 0.f, o2 = 0.f;
            #pragma unroll 8
            for (int v = 0; v < 32; v++) {
                float a = U[(v * 8 + ql) * 65 + node];
                const float* pvv = sv + (64 + 3 * v) * 64 + node;
                o0 += a * pvv[0];
                o1 += a * pvv[64];
                o2 += a * pvv[128];
            }
            int node_g = node0 + node;
            if (node_g < B) {
                float* o = out + (size_t)node_g * 240 + 64 + (qc * 8 + ql) * 3;
                o[0] = C1 * o0; o[1] = C1 * o1; o[2] = C1 * o2;
            }
        }
        __syncthreads();
    }

    // ---- Phase 4: out2. tv-GEMMs in (u-chunk of 8) x (j of 3), S in registers.
    float S[4][3][3];
    #pragma unroll
    for (int t = 0; t < 4; t++)
        #pragma unroll
        for (int i = 0; i < 3; i++)
            #pragma unroll
            for (int j = 0; j < 3; j++) S[t][i][j] = 0.f;

    float* wv2c = U;            // [32 v][8 ul][16 r] = 4096
    float* tvb  = U + 4096;     // [128 c][pitch 65] = 8320

    for (int uc = 0; uc < 4; uc++) {
        // stage W_vv2 chunk: wv2c[v*128 + ul*16 + r]
        for (int idx = tid; idx < 4096; idx += 256) {
            int v = idx >> 7;
            int rest = idx & 127;
            int ul = rest >> 4, rr = rest & 15;
            wv2c[idx] = Wvv2[((uc * 8 + ul) * 32 + v) * 16 + rr];
        }
        __syncthreads();
        #pragma unroll
        for (int j = 0; j < 3; j++) {
            float acc[4][8];
            #pragma unroll
            for (int i = 0; i < 4; i++)
                #pragma unroll
                for (int b = 0; b < 8; b++) acc[i][b] = 0.f;
            #pragma unroll 4
            for (int k = 0; k < 32; k++) {       // k = v channel
                float a[4], b[8];
                #pragma unroll
                for (int i = 0; i < 4; i++)
                    a[i] = sv[(64 + 3 * k + j) * 64 + ty + 16 * i];
                #pragma unroll
                for (int bi = 0; bi < 8; bi++)
                    b[bi] = wv2c[k * 128 + tx + 16 * bi];
                #pragma unroll
                for (int i = 0; i < 4; i++)
                    #pragma unroll
                    for (int bi = 0; bi < 8; bi++) acc[i][bi] += a[i] * b[bi];
            }
            // write tv chunk (col c = ul*16 + r = tx + 16*bi, pitch 65)
            #pragma unroll
            for (int i = 0; i < 4; i++)
                #pragma unroll
                for (int bi = 0; bi < 8; bi++)
                    tvb[(tx + 16 * bi) * 65 + ty + 16 * i] = acc[i][bi];
            __syncthreads();
            // accumulate S[t][i][j] += sum_{u in chunk} v[u,i] * tv[u,j,r]
            #pragma unroll
            for (int t = 0; t < 4; t++) {
                int it = tid + t * 256;   // 1024 items: (node, r)
                int node = it & 63;
                int r = it >> 6;
                #pragma unroll
                for (int ul = 0; ul < 8; ul++) {
                    float tvv = tvb[(ul * 16 + r) * 65 + node];
                    const float* pu_ = sv + (64 + 3 * (uc * 8 + ul)) * 64 + node;
                    S[t][0][j] += pu_[0]   * tvv;
                    S[t][1][j] += pu_[64]  * tvv;
                    S[t][2][j] += pu_[128] * tvv;
                }
            }
            __syncthreads();
        }
    }
    // finalize out2 via CG contraction
    const float C2R2 = (1.f / 32.f) * 0.7071067811865475f;
    const float C2R6 = (1.f / 32.f) * 0.4082482904638630f;
    #pragma unroll
    for (int t = 0; t < 4; t++) {
        int it = tid + t * 256;
        int node = node0 + (it & 63);
        int r = it >> 6;
        if (node < B) {
            float* o = out + (size_t)node * 240 + 160 + r * 5;
            o[0] = C2R2 * (S[t][0][1] + S[t][1][0]);
            o[1] = C2R2 * (S[t][1][2] + S[t][2][1]);
            o[2] = C2R6 * (2.f * S[t][2][2] - S[t][0][0] - S[t][1][1]);
            o[3] = C2R2 * (S[t][0][2] + S[t][2][0]);
            o[4] = C2R2 * (S[t][0][0] - S[t][1][1]);
        }
    }
}

// ------------------------------------------------------------------- launcher
extern "C" void kernel_launch(void* const* d_in, const int* in_sizes, int n_in,
                              void* d_out, int out_size)
{
    const float* x     = (const float*)d_in[0];
    const float* gates = (const float*)d_in[1];
    const float* Wss0  = (const float*)d_in[2];
    const float* Wsv1  = (const float*)d_in[3];
    const float* Wvv0  = (const float*)d_in[4];
    const float* Wvv2  = (const float*)d_in[5];
    float* out = (float*)d_out;

    int B = in_sizes[0] / 160;

    prep_pairs<<<1, 256>>>();
    prep_wc<<<KPAD, 64>>>(Wss0, Wvv0);

    size_t smem_bytes = (size_t)SMEM_FLOATS * sizeof(float);  // 107,648 B
    cudaFuncSetAttribute(k_main, cudaFuncAttributeMaxDynamicSharedMemorySize,
                         (int)smem_bytes);
    int grid = (B + 63) / 64;
    k_main<<<grid, 256, smem_bytes>>>(x, gates, Wsv1, Wvv2, out, B);
}

// round 2
// speedup vs baseline: 1.6930x; 1.6930x over previous
#include <cuda_runtime.h>
#include <math.h>
#include <stdint.h>

// ----------------------------------------------------------------------------
// NonLinearTSQ: gated tensor-square, tensor-core (tf32 mma.sync) version.
//   in : 64x0e + 32x1o   (160 floats/node)
//   out: 64x0e + 32x1o + 16x2e (240 floats/node), B = 32768
//
//   out0 = packed-symmetric quadratic features (K=2608->2624) x Wc[2624,64]
//   out1 = (s @ Wsv1) contracted with v, per 4-wide q chunks
//   out2 = (v_j @ Wvv2) -> tv, contracted with v_i, CG epilogue
// ----------------------------------------------------------------------------

#define KSS   2080
#define KREAL 2608
#define KPAD  2624          // 41 chunks of 64

__device__ __align__(16) float g_Wc[KPAD * 64];   // tf32-rounded packed weights
__device__ int g_puv[KPAD];                        // (type<<16)|(u<<8)|v

// ---------------------------------------------------------------- helpers
__device__ __forceinline__ uint32_t cvt_tf32(float x) {
    uint32_t u;
    asm("cvt.rna.tf32.f32 %0, %1;" : "=r"(u) : "f"(x));
    return u;
}

__device__ __forceinline__ void mma_tf32(float c[4],
                                         uint32_t a0, uint32_t a1,
                                         uint32_t a2, uint32_t a3,
                                         uint32_t b0, uint32_t b1) {
    asm volatile(
        "mma.sync.aligned.m16n8k8.row.col.f32.tf32.tf32.f32 "
        "{%0,%1,%2,%3}, {%4,%5,%6,%7}, {%8,%9}, {%0,%1,%2,%3};"
        : "+f"(c[0]), "+f"(c[1]), "+f"(c[2]), "+f"(c[3])
        : "r"(a0), "r"(a1), "r"(a2), "r"(a3), "r"(b0), "r"(b1));
}

// ---------------------------------------------------------------- prep kernel
__global__ void prep(const float* __restrict__ Wss0,
                     const float* __restrict__ Wvv0)
{
    __shared__ int sh_u, sh_v, sh_t;
    int k = blockIdx.x;
    if (threadIdx.x == 0) {
        int u = 0, v = 0, t = 2;
        if (k < KSS) {
            int rem = k, row = 64;
            while (rem >= row) { rem -= row; row--; }
            u = 64 - row; v = u + rem; t = 0;
        } else if (k < KREAL) {
            int rem = k - KSS, row = 32;
            while (rem >= row) { rem -= row; row--; }
            u = 32 - row; v = u + rem; t = 1;
        }
        sh_u = u; sh_v = v; sh_t = t;
        g_puv[k] = (t << 16) | (u << 8) | v;
    }
    __syncthreads();
    int p = threadIdx.x;
    int u = sh_u, v = sh_v, t = sh_t;
    const float C0 = 1.0f / sqrtf(5120.0f);
    const float RS3 = 0.5773502691896258f;
    float val = 0.0f;
    if (t == 0) {
        val = Wss0[(u * 64 + v) * 64 + p];
        if (u != v) val += Wss0[(v * 64 + u) * 64 + p];
        val *= C0;
    } else if (t == 1) {
        val = Wvv0[(u * 32 + v) * 64 + p];
        if (u != v) val += Wvv0[(v * 32 + u) * 64 + p];
        val *= C0 * RS3;
    }
    g_Wc[k * 64 + p] = __uint_as_float(cvt_tf32(val));
}

// ------------------------------------------------------------------ main kernel
// 64 nodes per block, 256 threads (8 warps).
// smem: sv[160][64] | U[12672] | gv[32]
#define U_FLOATS   12672
#define SMEM_FLOATS (160 * 64 + U_FLOATS + 32)

__global__ __launch_bounds__(256, 2)
void k_main(const float* __restrict__ x, const float* __restrict__ gates,
            const float* __restrict__ Wsv1, const float* __restrict__ Wvv2,
            float* __restrict__ out, int B)
{
    extern __shared__ float sm[];
    float* sv = sm;                  // [160][64]
    float* U  = sm + 160 * 64;       // scratch, 12672 floats
    float* gv = U + U_FLOATS;        // 32

    const int tid  = threadIdx.x;
    const int lane = tid & 31;
    const int warp = tid >> 5;
    const int gid  = lane >> 2;      // 0..7
    const int tig  = lane & 3;       // 0..3
    const int node0 = blockIdx.x * 64;

    // warp tile origins
    const int m0   = (warp & 3) * 16;    // node tile
    const int n0p2 = (warp >> 2) * 32;   // phase-2 output tile (N=64)
    const int n0w  = (warp >> 2) * 64;   // phase-3/4 output tile (N=128)

    if (tid < 32) gv[tid] = tanhf(gates[tid]);
    __syncthreads();

    // ---- Phase 1: load tile, nonlinearity, transpose to feature-major
    for (int idx = tid; idx < 2560; idx += 256) {
        int node = idx / 40;
        int fq = idx - node * 40;
        float4 xv = make_float4(0.f, 0.f, 0.f, 0.f);
        if (node0 + node < B)
            xv = *(const float4*)(x + (size_t)(node0 + node) * 160 + fq * 4);
        float vals[4] = {xv.x, xv.y, xv.z, xv.w};
        #pragma unroll
        for (int jj = 0; jj < 4; jj++) {
            int f = fq * 4 + jj;
            float val = vals[jj];
            if (f < 64) val = tanhf(val);
            else        val *= gv[(f - 64) / 3];
            sv[f * 64 + node] = val;
        }
    }
    __syncthreads();

    // =======================================================================
    // Phase 2: out0 = z[2624] x Wc[2624,64], tensor GEMM M=64,N=64
    // zbuf pitch 72, wbuf pitch 72 (tig*8+gid distinct mod 32 -> conflict-free)
    // =======================================================================
    float* zbuf = U;             // [64][72]
    float* wbuf = U + 64 * 72;   // [64][72]

    float c2a[4][4];
    #pragma unroll
    for (int j = 0; j < 4; j++)
        #pragma unroll
        for (int i = 0; i < 4; i++) c2a[j][i] = 0.f;

    for (int ck = 0; ck < 41; ck++) {
        int kbase = ck * 64;
        // build z chunk (tf32-rounded)
        #pragma unroll
        for (int t = 0; t < 16; t++) {
            int idx = tid + t * 256;
            int kk = idx >> 6;
            int node = idx & 63;
            int k = kbase + kk;
            int puv = g_puv[k];
            int typ = puv >> 16;
            int u = (puv >> 8) & 255, vch = puv & 255;
            float z = 0.f;
            if (typ == 0) {
                z = sv[u * 64 + node] * sv[vch * 64 + node];
            } else if (typ == 1) {
                const float* pa = sv + (64 + 3 * u) * 64 + node;
                const float* pb = sv + (64 + 3 * vch) * 64 + node;
                z = pa[0] * pb[0] + pa[64] * pb[64] + pa[128] * pb[128];
            }
            zbuf[kk * 72 + node] = __uint_as_float(cvt_tf32(z));
        }
        // stage Wc chunk (already tf32)
        #pragma unroll
        for (int t = 0; t < 4; t++) {
            int idx = tid + t * 256;
            int kk = idx >> 4;
            int p = (idx & 15) * 4;
            float4 w = *(const float4*)(g_Wc + (size_t)(kbase + kk) * 64 + p);
            *(float4*)(wbuf + kk * 72 + p) = w;
        }
        __syncthreads();
        // 8 k-steps of m16n8k8
        #pragma unroll
        for (int ks = 0; ks < 8; ks++) {
            int kb = ks * 8;
            uint32_t a0 = __float_as_uint(zbuf[(kb + tig) * 72 + m0 + gid]);
            uint32_t a1 = __float_as_uint(zbuf[(kb + tig) * 72 + m0 + gid + 8]);
            uint32_t a2 = __float_as_uint(zbuf[(kb + tig + 4) * 72 + m0 + gid]);
            uint32_t a3 = __float_as_uint(zbuf[(kb + tig + 4) * 72 + m0 + gid + 8]);
            #pragma unroll
            for (int j = 0; j < 4; j++) {
                uint32_t b0 = __float_as_uint(wbuf[(kb + tig) * 72 + n0p2 + j * 8 + gid]);
                uint32_t b1 = __float_as_uint(wbuf[(kb + tig + 4) * 72 + n0p2 + j * 8 + gid]);
                mma_tf32(c2a[j], a0, a1, a2, a3, b0, b1);
            }
        }
        __syncthreads();
    }
    // write out0
    {
        int nodeA = node0 + m0 + gid;
        int nodeB = nodeA + 8;
        #pragma unroll
        for (int j = 0; j < 4; j++) {
            int p = n0p2 + j * 8 + 2 * tig;
            if (nodeA < B)
                *(float2*)(out + (size_t)nodeA * 240 + p) = make_float2(c2a[j][0], c2a[j][1]);
            if (nodeB < B)
                *(float2*)(out + (size_t)nodeB * 240 + p) = make_float2(c2a[j][2], c2a[j][3]);
        }
    }

    // =======================================================================
    // Phase 3: out1. 8 chunks of 4 q's. GEMM M=64, N=128 (=32v x 4q), K=64.
    // B pitch 136; A' pitch 65.
    // =======================================================================
    const float C1 = 0.022097086912079612f;   // 1/sqrt(2048)
    for (int qc = 0; qc < 8; qc++) {
        // stage B: U[u*136 + v*4+ql]
        #pragma unroll
        for (int t = 0; t < 32; t++) {
            int idx = tid + t * 256;
            int u = idx >> 7;
            int col = idx & 127;
            int v = col >> 2, ql = col & 3;
            U[u * 136 + col] =
                __uint_as_float(cvt_tf32(Wsv1[u * 1024 + v * 32 + qc * 4 + ql]));
        }
        __syncthreads();
        float c[8][4];
        #pragma unroll
        for (int j = 0; j < 8; j++)
            #pragma unroll
            for (int i = 0; i < 4; i++) c[j][i] = 0.f;
        #pragma unroll
        for (int ks = 0; ks < 8; ks++) {
            int kb = ks * 8;
            uint32_t a0 = cvt_tf32(sv[(kb + tig) * 64 + m0 + gid]);
            uint32_t a1 = cvt_tf32(sv[(kb + tig) * 64 + m0 + gid + 8]);
            uint32_t a2 = cvt_tf32(sv[(kb + tig + 4) * 64 + m0 + gid]);
            uint32_t a3 = cvt_tf32(sv[(kb + tig + 4) * 64 + m0 + gid + 8]);
            #pragma unroll
            for (int j = 0; j < 8; j++) {
                int col = n0w + j * 8 + gid;
                uint32_t b0 = __float_as_uint(U[(kb + tig) * 136 + col]);
                uint32_t b1 = __float_as_uint(U[(kb + tig + 4) * 136 + col]);
                mma_tf32(c[j], a0, a1, a2, a3, b0, b1);
            }
        }
        __syncthreads();
        // write A' (reuse U), pitch 65
        #pragma unroll
        for (int j = 0; j < 8; j++) {
            int col = n0w + j * 8 + 2 * tig;
            U[col * 65 + m0 + gid]           = c[j][0];
            U[(col + 1) * 65 + m0 + gid]     = c[j][1];
            U[col * 65 + m0 + gid + 8]       = c[j][2];
            U[(col + 1) * 65 + m0 + gid + 8] = c[j][3];
        }
        __syncthreads();
        // epilogue: 256 items (node, ql)
        {
            int node = tid & 63;
            int ql = tid >> 6;
            float o0 = 0.f, o1 = 0.f, o2 = 0.f;
            #pragma unroll 8
            for (int v = 0; v < 32; v++) {
                float a = U[(v * 4 + ql) * 65 + node];
                const float* pvv = sv + (64 + 3 * v) * 64 + node;
                o0 += a * pvv[0];
                o1 += a * pvv[64];
                o2 += a * pvv[128];
            }
            int node_g = node0 + node;
            if (node_g < B) {
                float* o = out + (size_t)node_g * 240 + 64 + (qc * 4 + ql) * 3;
                o[0] = C1 * o0; o[1] = C1 * o1; o[2] = C1 * o2;
            }
        }
        __syncthreads();
    }

    // =======================================================================
    // Phase 4: out2. 4 u-chunks x 3 components. GEMM M=64, N=128, K=32.
    // B4 pitch 136 (4352 floats), tvb pitch 65 at U+4352 (8320 floats).
    // =======================================================================
    float S[4][9];
    #pragma unroll
    for (int t = 0; t < 4; t++)
        #pragma unroll
        for (int i = 0; i < 9; i++) S[t][i] = 0.f;

    float* B4  = U;
    float* tvb = U + 32 * 136;

    for (int uc = 0; uc < 4; uc++) {
        // stage B4[v*136 + ul*16 + r]
        #pragma unroll
        for (int t = 0; t < 16; t++) {
            int idx = tid + t * 256;
            int v = idx >> 7;
            int col = idx & 127;
            int ul = col >> 4, rr = col & 15;
            B4[v * 136 + col] =
                __uint_as_float(cvt_tf32(Wvv2[((uc * 8 + ul) * 32 + v) * 16 + rr]));
        }
        __syncthreads();
        #pragma unroll
        for (int j = 0; j < 3; j++) {
            float c[8][4];
            #pragma unroll
            for (int jj = 0; jj < 8; jj++)
                #pragma unroll
                for (int i = 0; i < 4; i++) c[jj][i] = 0.f;
            #pragma unroll
            for (int ks = 0; ks < 4; ks++) {
                int kb = ks * 8;
                uint32_t a0 = cvt_tf32(sv[(64 + 3 * (kb + tig) + j) * 64 + m0 + gid]);
                uint32_t a1 = cvt_tf32(sv[(64 + 3 * (kb + tig) + j) * 64 + m0 + gid + 8]);
                uint32_t a2 = cvt_tf32(sv[(64 + 3 * (kb + tig + 4) + j) * 64 + m0 + gid]);
                uint32_t a3 = cvt_tf32(sv[(64 + 3 * (kb + tig + 4) + j) * 64 + m0 + gid + 8]);
                #pragma unroll
                for (int jn = 0; jn < 8; jn++) {
                    int col = n0w + jn * 8 + gid;
                    uint32_t b0 = __float_as_uint(B4[(kb + tig) * 136 + col]);
                    uint32_t b1 = __float_as_uint(B4[(kb + tig + 4) * 136 + col]);
                    mma_tf32(c[jn], a0, a1, a2, a3, b0, b1);
                }
            }
            __syncthreads();   // prior S-accum reads of tvb done before overwrite
            #pragma unroll
            for (int jn = 0; jn < 8; jn++) {
                int col = n0w + jn * 8 + 2 * tig;
                tvb[col * 65 + m0 + gid]           = c[jn][0];
                tvb[(col + 1) * 65 + m0 + gid]     = c[jn][1];
                tvb[col * 65 + m0 + gid + 8]       = c[jn][2];
                tvb[(col + 1) * 65 + m0 + gid + 8] = c[jn][3];
            }
            __syncthreads();
            // S accumulation: 1024 items (node, r)
            #pragma unroll
            for (int t = 0; t < 4; t++) {
                int it = tid + t * 256;
                int node = it & 63;
                int r = it >> 6;
                #pragma unroll
                for (int ul = 0; ul < 8; ul++) {
                    float tvv = tvb[(ul * 16 + r) * 65 + node];
                    const float* pu_ = sv + (64 + 3 * (uc * 8 + ul)) * 64 + node;
                    S[t][0 * 3 + j] += pu_[0]   * tvv;
                    S[t][1 * 3 + j] += pu_[64]  * tvv;
                    S[t][2 * 3 + j] += pu_[128] * tvv;
                }
            }
            __syncthreads();
        }
    }
    // finalize out2 via CG contraction
    const float C2R2 = (1.f / 32.f) * 0.7071067811865475f;
    const float C2R6 = (1.f / 32.f) * 0.4082482904638630f;
    #pragma unroll
    for (int t = 0; t < 4; t++) {
        int it = tid + t * 256;
        int node = node0 + (it & 63);
        int r = it >> 6;
        if (node < B) {
            float* o = out + (size_t)node * 240 + 160 + r * 5;
            o[0] = C2R2 * (S[t][0 * 3 + 1] + S[t][1 * 3 + 0]);
            o[1] = C2R2 * (S[t][1 * 3 + 2] + S[t][2 * 3 + 1]);
            o[2] = C2R6 * (2.f * S[t][2 * 3 + 2] - S[t][0 * 3 + 0] - S[t][1 * 3 + 1]);
            o[3] = C2R2 * (S[t][0 * 3 + 2] + S[t][2 * 3 + 0]);
            o[4] = C2R2 * (S[t][0 * 3 + 0] - S[t][1 * 3 + 1]);
        }
    }
}

// ------------------------------------------------------------------- launcher
extern "C" void kernel_launch(void* const* d_in, const int* in_sizes, int n_in,
                              void* d_out, int out_size)
{
    const float* x     = (const float*)d_in[0];
    const float* gates = (const float*)d_in[1];
    const float* Wss0  = (const float*)d_in[2];
    const float* Wsv1  = (const float*)d_in[3];
    const float* Wvv0  = (const float*)d_in[4];
    const float* Wvv2  = (const float*)d_in[5];
    float* out = (float*)d_out;

    int B = in_sizes[0] / 160;

    prep<<<KPAD, 64>>>(Wss0, Wvv0);

    size_t smem_bytes = (size_t)SMEM_FLOATS * sizeof(float);  // 91,776 B
    cudaFuncSetAttribute(k_main, cudaFuncAttributeMaxDynamicSharedMemorySize,
                         (int)smem_bytes);
    int grid = (B + 63) / 64;
    k_main<<<grid, 256, smem_bytes>>>(x, gates, Wsv1, Wvv2, out, B);
}